// round 10
// baseline (speedup 1.0000x reference)
#include <cuda_runtime.h>
#include <cuda_bf16.h>
#include <cstdint>

// ===========================================================================
// MoE AG-scatter grouped GEMM via mma.sync bf16, 2-term fp32 split (3 products)
//   out[s,:] = x[token(s),:] @ W[e(s),:,:]^T
// R10 = R9 GEMM core (BK=32, 3 stages, XOR swizzle, CTA 128x128, 8 warps
//   4Mx2N, 2 CTAs/SM, persistent jobs, mid-chunk load placement) with the
//   per-chunk __syncthreads convoy replaced by PER-STAGE MBARRIER flow
//   control: full[s] via cp.async.mbarrier.arrive.noinc (count 256),
//   empty[s] via per-warp arrive (count 8). Warps slide independently.
//   Stage rotation is continuous across jobs (gc = jc*32 + c).
// ===========================================================================

#define NTOK   8192
#define TOPK   2
#define MTOT   (NTOK * TOPK)          // 16384
#define NDIM   1024
#define KDIM   1024
#define NEXP   8

#define BM     128
#define BN     128
#define BK     32                     // bf16 k per chunk
#define NCHUNK (KDIM / BK)            // 32
#define NSTAGE 3
#define NBLK   (NDIM / BN)            // 8
#define MAXTILES (MTOT / BM + NEXP)   // 136

#define RSTR   64                     // unpadded row stride (bytes)
#define OFF_AH 0
#define OFF_AL (128 * RSTR)
#define OFF_BH (2 * 128 * RSTR)
#define OFF_BL (3 * 128 * RSTR)
#define STAGE_BYTES (4 * 128 * RSTR)  // 32768
// stages | s_tok 512 | s_job 16 | mbarriers 64
#define SMEM_TOTAL  (NSTAGE * STAGE_BYTES + 512 + 16 + 64)

// ---------------- device-global scratch ------------------------------------
__device__ int g_token_of_row[MTOT];
__device__ int g_tile_e[MAXTILES];
__device__ int g_tile_row0[MAXTILES];
__device__ int g_tile_rows[MAXTILES];
__device__ int g_njobs;
__device__ int g_job;
__device__ __align__(16) __nv_bfloat16 g_A_hi[(size_t)NTOK * KDIM];
__device__ __align__(16) __nv_bfloat16 g_A_lo[(size_t)NTOK * KDIM];
__device__ __align__(16) __nv_bfloat16 g_W_hi[(size_t)NEXP * NDIM * KDIM];
__device__ __align__(16) __nv_bfloat16 g_W_lo[(size_t)NEXP * NDIM * KDIM];

// ---------------- helpers ---------------------------------------------------
__device__ __forceinline__ uint32_t smem_to_u32(const void* p) {
    uint32_t a;
    asm("{ .reg .u64 t; cvta.to.shared.u64 t, %1; cvt.u32.u64 %0, t; }"
        : "=r"(a) : "l"(p));
    return a;
}

#define CPA16(dst_u32, src_ptr) \
    asm volatile("cp.async.cg.shared.global [%0], [%1], 16;" \
        :: "r"(dst_u32), "l"(src_ptr))

// arrive-on-completion of all this thread's prior cp.asyncs (no count inc)
#define CPA_MBAR_ARRIVE(mbar) \
    asm volatile("cp.async.mbarrier.arrive.noinc.shared.b64 [%0];" \
        :: "r"((uint32_t)(mbar)) : "memory")

#define MBARRIER_INIT(mbar, cnt) \
    asm volatile("mbarrier.init.shared.b64 [%0], %1;" \
        :: "r"((uint32_t)(mbar)), "r"((uint32_t)(cnt)) : "memory")

#define MBAR_ARRIVE(mbar) \
    asm volatile("mbarrier.arrive.shared.b64 _, [%0];" \
        :: "r"((uint32_t)(mbar)) : "memory")

#define MBARRIER_WAIT_PARITY(mbar_smem_addr, phase_parity) do { \
    uint32_t _mbar = (uint32_t)(mbar_smem_addr); \
    uint32_t _parity = (uint32_t)(phase_parity); \
    uint32_t _done; \
    asm volatile( \
        "{ .reg .pred p;\n\t" \
        "mbarrier.try_wait.parity.acquire.cta.shared::cta.b64 p, [%1], %2;\n\t" \
        "selp.b32 %0, 1, 0, p; }" \
        : "=r"(_done) : "r"(_mbar), "r"(_parity) : "memory"); \
    if (!_done) { \
        asm volatile( \
            "{ .reg .pred P1;\n\t" \
            "WAIT_LOOP_%=:\n\t" \
            "mbarrier.try_wait.parity.acquire.cta.shared::cta.b64 P1, [%0], %1, 0x989680;\n\t" \
            "@P1 bra.uni WAIT_DONE_%=;\n\t" \
            "bra.uni WAIT_LOOP_%=;\n\t" \
            "WAIT_DONE_%=: }" \
            :: "r"(_mbar), "r"(_parity) : "memory"); \
    } \
} while (0)

__device__ __forceinline__ void ldsm_x4(uint32_t r[4], uint32_t addr) {
    asm volatile("ldmatrix.sync.aligned.m8n8.x4.shared.b16 {%0,%1,%2,%3}, [%4];"
        : "=r"(r[0]), "=r"(r[1]), "=r"(r[2]), "=r"(r[3]) : "r"(addr));
}

__device__ __forceinline__ void mma_bf16(float d[4],
    const uint32_t a[4], uint32_t b0, uint32_t b1)
{
    asm volatile(
        "mma.sync.aligned.m16n8k16.row.col.f32.bf16.bf16.f32 "
        "{%0,%1,%2,%3}, {%4,%5,%6,%7}, {%8,%9}, {%0,%1,%2,%3};"
        : "+f"(d[0]), "+f"(d[1]), "+f"(d[2]), "+f"(d[3])
        : "r"(a[0]), "r"(a[1]), "r"(a[2]), "r"(a[3]), "r"(b0), "r"(b1));
}

__device__ __forceinline__ void split_store(float4 v, __nv_bfloat16* hi,
                                            __nv_bfloat16* lo, size_t o)
{
    __nv_bfloat16 h0 = __float2bfloat16(v.x), h1 = __float2bfloat16(v.y);
    __nv_bfloat16 h2 = __float2bfloat16(v.z), h3 = __float2bfloat16(v.w);
    __nv_bfloat16 l0 = __float2bfloat16(v.x - __bfloat162float(h0));
    __nv_bfloat16 l1 = __float2bfloat16(v.y - __bfloat162float(h1));
    __nv_bfloat16 l2 = __float2bfloat16(v.z - __bfloat162float(h2));
    __nv_bfloat16 l3 = __float2bfloat16(v.w - __bfloat162float(h3));
    *(ushort4*)(hi + o) = make_ushort4(
        __bfloat16_as_ushort(h0), __bfloat16_as_ushort(h1),
        __bfloat16_as_ushort(h2), __bfloat16_as_ushort(h3));
    *(ushort4*)(lo + o) = make_ushort4(
        __bfloat16_as_ushort(l0), __bfloat16_as_ushort(l1),
        __bfloat16_as_ushort(l2), __bfloat16_as_ushort(l3));
}

// ---------------- fused prep (2 float4 per thread, MLP=2) -------------------
#define WBLK 4096
#define ABLK 4096
#define MBLK (MTOT / 256)             // 64
#define PREP_GRID (WBLK + ABLK + MBLK + 1)

__global__ __launch_bounds__(256) void prep_all(
    const float* __restrict__ x, const float* __restrict__ w,
    const int* __restrict__ scatter, const int* __restrict__ splits)
{
    int b = blockIdx.x;
    if (b < WBLK + ABLK) {
        const bool isW = (b < WBLK);
        const float* src = isW ? w : x;
        __nv_bfloat16* hi = isW ? g_W_hi : g_A_hi;
        __nv_bfloat16* lo = isW ? g_W_lo : g_A_lo;
        size_t q = ((size_t)(isW ? b : b - WBLK) * 512 + threadIdx.x);
        size_t o0 = q * 4;
        size_t o1 = (q + 256) * 4;
        float4 v0 = *(const float4*)(src + o0);
        float4 v1 = *(const float4*)(src + o1);
        split_store(v0, hi, lo, o0);
        split_store(v1, hi, lo, o1);
    } else if (b < WBLK + ABLK + MBLK) {
        int f = (b - WBLK - ABLK) * 256 + threadIdx.x;
        g_token_of_row[scatter[f]] = f / TOPK;
    } else if (threadIdx.x == 0) {
        int cum = 0, t = 0;
        for (int e = 0; e < NEXP; e++) {
            int cnt = splits[e];
            for (int r0 = 0; r0 < cnt; r0 += BM) {
                g_tile_e[t] = e;
                g_tile_row0[t] = cum + r0;
                g_tile_rows[t] = (cnt - r0 < BM) ? (cnt - r0) : BM;
                t++;
            }
            cum += cnt;
        }
        g_njobs = t * NBLK;
        g_job = 0;
    }
}

// ---------------- main GEMM --------------------------------------------------
__device__ __forceinline__ void load_stage(uint32_t sbuf, int c, int wbase,
                                           const int* s_tok, int tid)
{
    const size_t kb = (size_t)c * BK;
    #pragma unroll
    for (int i = 0; i < 8; i++) {
        int o   = tid + i * 256;          // 0..2047
        int t4  = o >> 9;                 // 0=Ah,1=Al,2=Bh,3=Bl
        int r   = (o >> 2) & 127;
        int seg = o & 3;
        int sw  = seg ^ ((r >> 1) & 3);   // XOR swizzle
        uint32_t dst = sbuf + t4 * (128 * RSTR) + r * RSTR + sw * 16;
        const char* src;
        if (t4 < 2) {
            int tok = s_tok[r];
            const __nv_bfloat16* base = (t4 == 0) ? g_A_hi : g_A_lo;
            src = (const char*)(base + (size_t)tok * KDIM + kb) + seg * 16;
        } else {
            const __nv_bfloat16* base = (t4 == 2) ? g_W_hi : g_W_lo;
            src = (const char*)(base + (size_t)(wbase + r) * KDIM + kb) + seg * 16;
        }
        CPA16(dst, src);
    }
}

__global__ __launch_bounds__(256, 2) void moe_gemm_mma(float* __restrict__ out)
{
    extern __shared__ char smem_raw[];
    const uint32_t stage0 = smem_to_u32(smem_raw);
    int* s_tok = (int*)(smem_raw + NSTAGE * STAGE_BYTES);
    int* s_job = (int*)(smem_raw + NSTAGE * STAGE_BYTES + 512);
    const uint32_t mbar0 = stage0 + NSTAGE * STAGE_BYTES + 512 + 16;
    // full[s] = mbar0 + s*8 ; empty[s] = mbar0 + 24 + s*8
    #define FULLB(s)  (mbar0 + (uint32_t)(s) * 8u)
    #define EMPTYB(s) (mbar0 + 24u + (uint32_t)(s) * 8u)

    const int tid  = threadIdx.x;
    const int wid  = tid >> 5;
    const int lane = tid & 31;
    const int wm   = wid & 3;          // 4 warps along M (32 rows each)
    const int wn   = wid >> 2;         // 2 warps along N (64 cols each)

    if (tid == 0) {
        #pragma unroll
        for (int s = 0; s < 3; s++) {
            MBARRIER_INIT(FULLB(s), 256);   // all threads' cp.async completions
            MBARRIER_INIT(EMPTYB(s), 8);    // one arrive per warp
        }
    }
    __syncthreads();

    // ldmatrix lane rows + per-row swizzle masks
    const int a_r   = (lane & 7) + ((lane >> 3) & 1) * 8;
    const int a_c16 = lane >> 4;
    uint32_t rowA[2]; int mA[2];
    #pragma unroll
    for (int mt = 0; mt < 2; mt++) {
        int r = wm * 32 + mt * 16 + a_r;
        rowA[mt] = r * RSTR;
        mA[mt] = (r >> 1) & 3;
    }
    const int b_r   = (lane & 7) + ((lane >> 4) & 1) * 8;
    const int b_k16 = (lane >> 3) & 1;
    uint32_t rowB[4]; int mB[4];
    #pragma unroll
    for (int np = 0; np < 4; np++) {
        int r = wn * 64 + np * 16 + b_r;
        rowB[np] = r * RSTR;
        mB[np] = (r >> 1) & 3;
    }

    const int njobs = g_njobs;
    int jc = 0;                         // per-CTA job counter (continuous gc)

    while (true) {
        __syncthreads();                // s_tok/s_job free from previous job
        if (tid == 0) *s_job = atomicAdd(&g_job, 1);
        __syncthreads();
        const int job = *s_job;
        if (job >= njobs) break;

        const int tile = job >> 3;      // NBLK = 8
        const int nb   = job & 7;
        const int nrows = g_tile_rows[tile];
        const int row0  = g_tile_row0[tile];
        const int e     = g_tile_e[tile];
        const int n0    = nb * BN;
        const int wbase = e * NDIM + n0;

        if (tid < 128)
            s_tok[tid] = (tid < nrows) ? g_token_of_row[row0 + tid] : 0;
        __syncthreads();

        float acc[2][8][4];
        #pragma unroll
        for (int mt = 0; mt < 2; mt++)
            #pragma unroll
            for (int nt = 0; nt < 8; nt++)
                #pragma unroll
                for (int q = 0; q < 4; q++)
                    acc[mt][nt][q] = 0.0f;

        const int gc0 = jc * NCHUNK;

        // prologue: 2 stage-loads, continuous rotation
        #pragma unroll
        for (int p = 0; p < 2; p++) {
            const int l = gc0 + p;
            const int t = l % 3;
            const int n = l / 3;
            if (n > 0) MBARRIER_WAIT_PARITY(EMPTYB(t), (n - 1) & 1);
            load_stage(stage0 + t * STAGE_BYTES, p, wbase, s_tok, tid);
            CPA_MBAR_ARRIVE(FULLB(t));
        }

        for (int c = 0; c < NCHUNK; c++) {
            const int gc = gc0 + c;
            const int s  = gc % 3;
            const int u  = gc / 3;
            const uint32_t sbuf = stage0 + s * STAGE_BYTES;

            MBARRIER_WAIT_PARITY(FULLB(s), u & 1);

            // ---- ks = 0 half ----
            {
                uint32_t Ah[2][4], Al[2][4];
                #pragma unroll
                for (int mt = 0; mt < 2; mt++) {
                    const uint32_t ao = rowA[mt] +
                        (uint32_t)((a_c16 ^ mA[mt]) << 4);
                    ldsm_x4(Ah[mt], sbuf + OFF_AH + ao);
                    ldsm_x4(Al[mt], sbuf + OFF_AL + ao);
                }
                #pragma unroll
                for (int np = 0; np < 4; np++) {
                    const uint32_t bo = rowB[np] +
                        (uint32_t)((b_k16 ^ mB[np]) << 4);
                    uint32_t Bh[4], Bl[4];
                    ldsm_x4(Bh, sbuf + OFF_BH + bo);
                    ldsm_x4(Bl, sbuf + OFF_BL + bo);
                    #pragma unroll
                    for (int mt = 0; mt < 2; mt++) {
                        float* d0 = acc[mt][2 * np];
                        float* d1 = acc[mt][2 * np + 1];
                        mma_bf16(d0, Ah[mt], Bh[0], Bh[1]);
                        mma_bf16(d1, Ah[mt], Bh[2], Bh[3]);
                        mma_bf16(d0, Ah[mt], Bl[0], Bl[1]);
                        mma_bf16(d1, Ah[mt], Bl[2], Bl[3]);
                        mma_bf16(d0, Al[mt], Bh[0], Bh[1]);
                        mma_bf16(d1, Al[mt], Bh[2], Bh[3]);
                    }
                }
            }

            // ---- producer: fill stage (gc+2)%3 while ks=0 MMAs drain ----
            if (c + 2 < NCHUNK) {
                const int l = gc + 2;
                const int t = l % 3;
                const int n = l / 3;
                if (n > 0) MBARRIER_WAIT_PARITY(EMPTYB(t), (n - 1) & 1);
                load_stage(stage0 + t * STAGE_BYTES, c + 2, wbase, s_tok, tid);
                CPA_MBAR_ARRIVE(FULLB(t));
            }

            // ---- ks = 1 half ----
            {
                uint32_t Ah[2][4], Al[2][4];
                #pragma unroll
                for (int mt = 0; mt < 2; mt++) {
                    const uint32_t ao = rowA[mt] +
                        (uint32_t)(((a_c16 + 2) ^ mA[mt]) << 4);
                    ldsm_x4(Ah[mt], sbuf + OFF_AH + ao);
                    ldsm_x4(Al[mt], sbuf + OFF_AL + ao);
                }
                #pragma unroll
                for (int np = 0; np < 4; np++) {
                    const uint32_t bo = rowB[np] +
                        (uint32_t)(((b_k16 + 2) ^ mB[np]) << 4);
                    uint32_t Bh[4], Bl[4];
                    ldsm_x4(Bh, sbuf + OFF_BH + bo);
                    ldsm_x4(Bl, sbuf + OFF_BL + bo);
                    #pragma unroll
                    for (int mt = 0; mt < 2; mt++) {
                        float* d0 = acc[mt][2 * np];
                        float* d1 = acc[mt][2 * np + 1];
                        mma_bf16(d0, Ah[mt], Bh[0], Bh[1]);
                        mma_bf16(d1, Ah[mt], Bh[2], Bh[3]);
                        mma_bf16(d0, Ah[mt], Bl[0], Bl[1]);
                        mma_bf16(d1, Ah[mt], Bl[2], Bl[3]);
                        mma_bf16(d0, Al[mt], Bh[0], Bh[1]);
                        mma_bf16(d1, Al[mt], Bh[2], Bh[3]);
                    }
                }
            }

            // warp done reading stage s (arrive has release semantics)
            if (lane == 0) MBAR_ARRIVE(EMPTYB(s));
        }

        // epilogue (no CTA barrier; next-job sync is at loop top)
        const int g = lane >> 2;
        const int t = lane & 3;
        #pragma unroll
        for (int mt = 0; mt < 2; mt++) {
            const int mBase = wm * 32 + mt * 16;
            const int m0 = mBase + g;
            const int m1 = mBase + g + 8;
            float* r0p = out + (size_t)(row0 + m0) * NDIM + n0 + wn * 64 + 2 * t;
            float* r1p = out + (size_t)(row0 + m1) * NDIM + n0 + wn * 64 + 2 * t;
            #pragma unroll
            for (int nt = 0; nt < 8; nt++) {
                if (m0 < nrows) {
                    float2 v; v.x = acc[mt][nt][0]; v.y = acc[mt][nt][1];
                    *(float2*)(r0p + nt * 8) = v;
                }
                if (m1 < nrows) {
                    float2 v; v.x = acc[mt][nt][2]; v.y = acc[mt][nt][3];
                    *(float2*)(r1p + nt * 8) = v;
                }
            }
        }

        jc++;
    }
    #undef FULLB
    #undef EMPTYB
}

// ---------------------------------------------------------------------------
extern "C" void kernel_launch(void* const* d_in, const int* in_sizes, int n_in,
                              void* d_out, int out_size) {
    const float* x       = (const float*)d_in[0];
    const float* weights = (const float*)d_in[1];
    const int*   scatter = (const int*)d_in[2];
    const int*   splits  = (const int*)d_in[3];
    float*       out     = (float*)d_out;
    (void)in_sizes; (void)n_in; (void)out_size;

    cudaFuncSetAttribute(moe_gemm_mma,
                         cudaFuncAttributeMaxDynamicSharedMemorySize, SMEM_TOTAL);

    prep_all<<<PREP_GRID, 256>>>(x, weights, scatter, splits);
    moe_gemm_mma<<<304, 256, SMEM_TOTAL>>>(out);   // persistent, 2 CTAs/SM
}